// round 1
// baseline (speedup 1.0000x reference)
#include <cuda_runtime.h>

// Fused 2-layer MLP (TokenEmbedding):
//   rows M = 512*3*128 = 196608
//   h  = relu(X[M,192] @ W0[192,1024] + b0)   (h never hits HBM)
//   out= relu(h @ W1[1024,256] + b1)          -> [M,256] fp32
//
// One CTA: TM=64 rows, 256 threads. Loop over 16 hidden chunks of HC=64:
//   stage W0[:,chunk], W1[chunk,:] in smem, compute h-chunk into smem (relu),
//   accumulate partial GEMM2 into per-thread registers (64 accums/thread).
// All math fp32 FFMA => numerically matches the fp32 reference.

#define THREADS 256
#define TM      64
#define HC      64
#define K1      192
#define HID     1024
#define EMB     256
#define NCHUNK  (HID / HC)   // 16

#define XS_STRIDE 196        // 192 + 4 pad (16B aligned rows, bank-skewed)
#define HS_STRIDE 68         // 64 + 4 pad
#define W1_STRIDE 260        // 256 + 4 pad

#define XS_OFF  0
#define W0S_OFF (XS_OFF  + TM * XS_STRIDE)        // 12544
#define W1S_OFF (W0S_OFF + K1 * HC)               // 12544 + 12288 = 24832
#define HS_OFF  (W1S_OFF + HC * W1_STRIDE)        // 24832 + 16640 = 41472
#define SMEM_FLOATS (HS_OFF + TM * HS_STRIDE)     // 41472 + 4352 = 45824
#define SMEM_BYTES  (SMEM_FLOATS * 4)             // 183296

__global__ void __launch_bounds__(THREADS, 1)
token_embedding_fused_kernel(const float* __restrict__ x,
                             const float* __restrict__ W0,
                             const float* __restrict__ b0,
                             const float* __restrict__ W1,
                             const float* __restrict__ b1,
                             float* __restrict__ out)
{
    extern __shared__ float smem[];
    float* xs  = smem + XS_OFF;    // [TM][XS_STRIDE]
    float* w0s = smem + W0S_OFF;   // [K1][HC]
    float* w1s = smem + W1S_OFF;   // [HC][W1_STRIDE]
    float* hs  = smem + HS_OFF;    // [TM][HS_STRIDE]

    const int tid  = threadIdx.x;
    const int row0 = blockIdx.x * TM;   // global row base (row = (b*3+blk)*128 + tok)

    // ---------------- load X tile [TM x 192] (transposed gather) ----------------
    // x strides: bin=1, tok=64, ch=8192, (b*3+blk)=24576. feature f = ch*64 + bin.
    {
        const float4* __restrict__ x4 = (const float4*)x;
        #pragma unroll
        for (int i = tid; i < TM * 3 * 16; i += THREADS) {
            int v    = i & 15;          // float4 within 64-bin run
            int ch   = (i >> 4) % 3;
            int m    = i / 48;
            int rowg = row0 + m;
            int bblk = rowg >> 7;       // / 128
            int tok  = rowg & 127;
            float4 val = x4[bblk * 6144 + ch * 2048 + tok * 16 + v];
            *(float4*)(xs + m * XS_STRIDE + ch * 64 + v * 4) = val;
        }
    }

    // GEMM2 output ownership: ty = tid/16 -> rows ty*4..+3 ; tx = tid%16 ->
    // columns {tx + 16*j, j=0..15} (strided => conflict-free w1s reads,
    // coalesced half-warp stores).
    const int ty = tid >> 4;
    const int tx = tid & 15;

    float acc[4][16];
    #pragma unroll
    for (int r = 0; r < 4; r++)
        #pragma unroll
        for (int j = 0; j < 16; j++)
            acc[r][j] = 0.0f;

    // GEMM1 ownership: ryh = tid/16 -> rows ryh*4..+3 ; cxh = tid%16 ->
    // h-columns cxh*4..+3 within the chunk.
    const int ryh = ty;
    const int cxh = tx;

    for (int c = 0; c < NCHUNK; c++) {
        const int hbase = c * HC;

        // ---- stage W0[:, hbase..hbase+63]  ([192][64], rows contiguous) ----
        {
            const float4* __restrict__ w04 = (const float4*)W0;
            #pragma unroll
            for (int i = tid; i < K1 * 16; i += THREADS) {
                int k = i >> 4;
                int v = i & 15;
                float4 val = w04[k * (HID / 4) + (hbase >> 2) + v];
                *(float4*)(w0s + k * HC + v * 4) = val;
            }
        }
        // ---- stage W1[hbase..hbase+63, :]  ([64][256]) ----
        {
            const float4* __restrict__ w14 = (const float4*)W1;
            #pragma unroll
            for (int i = tid; i < HC * 64; i += THREADS) {
                int kk = i >> 6;
                int v  = i & 63;
                float4 val = w14[(hbase + kk) * (EMB / 4) + v];
                *(float4*)(w1s + kk * W1_STRIDE + v * 4) = val;
            }
        }
        __syncthreads();

        // ---- GEMM1: h-chunk [64 x 64] = xs @ w0s (+b0, relu) ----
        {
            float acc1[4][4];
            #pragma unroll
            for (int r = 0; r < 4; r++) {
                #pragma unroll
                for (int cc = 0; cc < 4; cc++)
                    acc1[r][cc] = b0[hbase + cxh * 4 + cc];
            }
            #pragma unroll 4
            for (int k = 0; k < K1; k++) {
                float a0 = xs[(ryh * 4 + 0) * XS_STRIDE + k];
                float a1 = xs[(ryh * 4 + 1) * XS_STRIDE + k];
                float a2 = xs[(ryh * 4 + 2) * XS_STRIDE + k];
                float a3 = xs[(ryh * 4 + 3) * XS_STRIDE + k];
                float4 w = *(const float4*)(w0s + k * HC + cxh * 4);
                acc1[0][0] = fmaf(a0, w.x, acc1[0][0]);
                acc1[0][1] = fmaf(a0, w.y, acc1[0][1]);
                acc1[0][2] = fmaf(a0, w.z, acc1[0][2]);
                acc1[0][3] = fmaf(a0, w.w, acc1[0][3]);
                acc1[1][0] = fmaf(a1, w.x, acc1[1][0]);
                acc1[1][1] = fmaf(a1, w.y, acc1[1][1]);
                acc1[1][2] = fmaf(a1, w.z, acc1[1][2]);
                acc1[1][3] = fmaf(a1, w.w, acc1[1][3]);
                acc1[2][0] = fmaf(a2, w.x, acc1[2][0]);
                acc1[2][1] = fmaf(a2, w.y, acc1[2][1]);
                acc1[2][2] = fmaf(a2, w.z, acc1[2][2]);
                acc1[2][3] = fmaf(a2, w.w, acc1[2][3]);
                acc1[3][0] = fmaf(a3, w.x, acc1[3][0]);
                acc1[3][1] = fmaf(a3, w.y, acc1[3][1]);
                acc1[3][2] = fmaf(a3, w.z, acc1[3][2]);
                acc1[3][3] = fmaf(a3, w.w, acc1[3][3]);
            }
            #pragma unroll
            for (int r = 0; r < 4; r++) {
                float4 hv;
                hv.x = fmaxf(acc1[r][0], 0.0f);
                hv.y = fmaxf(acc1[r][1], 0.0f);
                hv.z = fmaxf(acc1[r][2], 0.0f);
                hv.w = fmaxf(acc1[r][3], 0.0f);
                *(float4*)(hs + (ryh * 4 + r) * HS_STRIDE + cxh * 4) = hv;
            }
        }
        __syncthreads();

        // ---- GEMM2 partial: acc += h-chunk @ w1s ----
        #pragma unroll 2
        for (int kk = 0; kk < HC; kk++) {
            float h0 = hs[(ty * 4 + 0) * HS_STRIDE + kk];
            float h1 = hs[(ty * 4 + 1) * HS_STRIDE + kk];
            float h2 = hs[(ty * 4 + 2) * HS_STRIDE + kk];
            float h3 = hs[(ty * 4 + 3) * HS_STRIDE + kk];
            #pragma unroll
            for (int j = 0; j < 16; j++) {
                float w = w1s[kk * W1_STRIDE + j * 16 + tx];
                acc[0][j] = fmaf(h0, w, acc[0][j]);
                acc[1][j] = fmaf(h1, w, acc[1][j]);
                acc[2][j] = fmaf(h2, w, acc[2][j]);
                acc[3][j] = fmaf(h3, w, acc[3][j]);
            }
        }
        __syncthreads();   // protect w0s/w1s/hs before next chunk overwrites
    }

    // ---------------- epilogue: +b1, relu, store ----------------
    #pragma unroll
    for (int r = 0; r < 4; r++) {
        const int rowg = row0 + ty * 4 + r;
        float* orow = out + (size_t)rowg * EMB;
        #pragma unroll
        for (int j = 0; j < 16; j++) {
            int e = j * 16 + tx;
            orow[e] = fmaxf(acc[r][j] + b1[e], 0.0f);
        }
    }
}

extern "C" void kernel_launch(void* const* d_in, const int* in_sizes, int n_in,
                              void* d_out, int out_size)
{
    const float* x  = (const float*)d_in[0];
    const float* W0 = (const float*)d_in[1];
    const float* b0 = (const float*)d_in[2];
    const float* W1 = (const float*)d_in[3];
    const float* b1 = (const float*)d_in[4];
    float* out = (float*)d_out;

    static bool configured = false;
    if (!configured) {
        cudaFuncSetAttribute(token_embedding_fused_kernel,
                             cudaFuncAttributeMaxDynamicSharedMemorySize,
                             SMEM_BYTES);
        configured = true;
    }

    const int M = 512 * 3 * 128;         // 196608 rows
    dim3 grid(M / TM);                   // 3072 CTAs
    token_embedding_fused_kernel<<<grid, THREADS, SMEM_BYTES>>>(
        x, W0, b0, W1, b1, out);
}

// round 4
// speedup vs baseline: 2.6265x; 2.6265x over previous
#include <cuda_runtime.h>
#include <cuda_bf16.h>
#include <cstdint>

// Fused 2-layer MLP via mma.sync bf16 (hi/lo split, 3 products).
//   out = relu(relu(X@W0+b0)@W1+b1); X:[196608,192] W0:[192,1024] W1:[1024,256]
// CTA: 64 rows, 256 threads (8 warps). Hidden chunked by 64.
// NOTE: tcgen05 is unavailable (harness PTX target is sm_100, not sm_100a);
// warp-level HMMA is the fastest legal tensor path.

#define K1   192
#define HID  1024
#define EMB  256
#define NCH  16

#define XS_W  196     // words (b32) per row of Xs/W0s: 392 bf16 + pad -> conflict-free
#define HS_W  68      // words per row of hs/w1s: 136 bf16

// smem byte offsets (16B aligned)
#define SM_B0S 0                      // 4096
#define SM_B1S 4096                   // 1024
#define SM_XS  5120                   // 64*784  = 50176
#define SM_W0S 55296                  // 64*784  = 50176
#define SM_HS  105472                 // 64*272  = 17408
#define SM_W1S 122880                 // 256*272 = 69632
#define SM_TOTAL 192512

// Pre-split weights, [n][k] k-major, k' = [hi | lo]
__device__ __align__(16) __nv_bfloat16 g_B1[HID * 384];    // W0^T
__device__ __align__(16) __nv_bfloat16 g_B2[EMB * 2048];   // W1^T

__device__ __forceinline__ void cpa16(uint32_t dst, const void* src) {
    asm volatile("cp.async.cg.shared.global [%0], [%1], 16;" :: "r"(dst), "l"(src) : "memory");
}
#define CP_COMMIT() asm volatile("cp.async.commit_group;" ::: "memory")
#define CP_WAIT1()  asm volatile("cp.async.wait_group 1;" ::: "memory")
#define CP_WAIT0()  asm volatile("cp.async.wait_group 0;" ::: "memory")

__device__ __forceinline__ uint32_t smem_u32(const void* p) {
    uint32_t a;
    asm("{ .reg .u64 t; cvta.to.shared.u64 t, %1; cvt.u32.u64 %0, t; }" : "=r"(a) : "l"(p));
    return a;
}

__device__ __forceinline__ void mma16816(float* c,
    uint32_t a0, uint32_t a1, uint32_t a2, uint32_t a3, uint32_t b0, uint32_t b1)
{
    asm volatile("mma.sync.aligned.m16n8k16.row.col.f32.bf16.bf16.f32 "
        "{%0,%1,%2,%3}, {%4,%5,%6,%7}, {%8,%9}, {%0,%1,%2,%3};"
        : "+f"(c[0]), "+f"(c[1]), "+f"(c[2]), "+f"(c[3])
        : "r"(a0), "r"(a1), "r"(a2), "r"(a3), "r"(b0), "r"(b1));
}

// ---------------- weight prep: hi/lo split, transposed to [n][k] ----------------
__global__ void prep_kernel(const float* __restrict__ W0, const float* __restrict__ W1) {
    int stride = gridDim.x * blockDim.x;
    int t0 = blockIdx.x * blockDim.x + threadIdx.x;
    for (int i = t0; i < HID * K1; i += stride) {
        int n = i / K1, k = i % K1;
        float w = W0[k * HID + n];
        __nv_bfloat16 h = __float2bfloat16(w);
        g_B1[n * 384 + k]       = h;
        g_B1[n * 384 + 192 + k] = __float2bfloat16(w - __bfloat162float(h));
    }
    for (int i = t0; i < EMB * HID; i += stride) {
        int n = i / HID, k = i % HID;
        float w = W1[k * EMB + n];
        __nv_bfloat16 h = __float2bfloat16(w);
        g_B2[n * 2048 + k]        = h;
        g_B2[n * 2048 + 1024 + k] = __float2bfloat16(w - __bfloat162float(h));
    }
}

// ---------------- chunk loaders (cp.async) ----------------
__device__ __forceinline__ void load_w0(uint32_t sb, int c, int tid) {
    const __nv_bfloat16* base = g_B1 + (size_t)c * 64 * 384;
    #pragma unroll
    for (int i = tid; i < 3072; i += 256) {           // 64 rows x 48 x 16B
        int n = i / 48, u = i % 48;
        cpa16(sb + SM_W0S + n * 784 + u * 16, base + n * 384 + u * 8);
    }
    CP_COMMIT();
}
__device__ __forceinline__ void load_w1(uint32_t sb, int c, int tid) {
    const __nv_bfloat16* base = g_B2 + c * 64;
    #pragma unroll
    for (int i = tid; i < 4096; i += 256) {           // 256 rows x (8 hi + 8 lo) x 16B
        int n = i / 16, u = i % 16, sp = u >> 3, uu = u & 7;
        cpa16(sb + SM_W1S + n * 272 + sp * 128 + uu * 16,
              base + n * 2048 + sp * 1024 + uu * 8);
    }
    CP_COMMIT();
}

// ---------------- main fused kernel ----------------
__global__ void __launch_bounds__(256, 1)
mlp_kernel(const float* __restrict__ x, const float* __restrict__ b0,
           const float* __restrict__ b1, float* __restrict__ out)
{
    extern __shared__ char smem[];
    const uint32_t sb = smem_u32(smem);
    const int tid  = threadIdx.x;
    const int lane = tid & 31;
    const int w    = tid >> 5;
    const int r    = lane >> 2;     // fragment row 0..7
    const int q    = lane & 3;      // fragment quad col
    const int wm   = w >> 1;        // 0..3 -> m0
    const int wn   = w & 1;         // 0..1
    const int m0   = wm * 16;
    const int n1   = wn * 32;       // GEMM1 col base
    const int n2   = wn * 128;      // GEMM2 col base

    const int slice   = blockIdx.x >> 1;
    const int tokbase = (blockIdx.x & 1) * 64;

    uint32_t*       xsw  = (uint32_t*)(smem + SM_XS);
    const uint32_t* w0sw = (const uint32_t*)(smem + SM_W0S);
    uint32_t*       hsw  = (uint32_t*)(smem + SM_HS);
    const uint32_t* w1sw = (const uint32_t*)(smem + SM_W1S);
    float*          b0s  = (float*)(smem + SM_B0S);
    float*          b1s  = (float*)(smem + SM_B1S);

    // prefetch chunk 0 weights
    load_w0(sb, 0, tid);
    load_w1(sb, 0, tid);

    // X slice -> Xs (bf16 hi [0..191] || lo [192..383], per row, stride 196 words)
    {
        const float2* x2 = (const float2*)(x + (size_t)slice * 24576);
        #pragma unroll 4
        for (int i = tid; i < 6144; i += 256) {
            int m = i / 96, u = i % 96;
            int ch = u >> 5, bp = u & 31;
            float2 v = x2[(ch * 8192 + (tokbase + m) * 64) / 2 + bp];
            __nv_bfloat162 h2 = __floats2bfloat162_rn(v.x, v.y);
            __nv_bfloat162 l2 = __floats2bfloat162_rn(v.x - __bfloat162float(h2.x),
                                                      v.y - __bfloat162float(h2.y));
            int fw = (ch * 64) / 2 + bp;             // word index of feature pair
            xsw[m * XS_W + fw]      = *(uint32_t*)&h2;
            xsw[m * XS_W + 96 + fw] = *(uint32_t*)&l2;
        }
        for (int i = tid; i < 1024; i += 256) b0s[i] = b0[i];
        for (int i = tid; i < 256;  i += 256) b1s[i] = b1[i];
    }

    float acc2[16][4];
    #pragma unroll
    for (int j = 0; j < 16; j++)
        #pragma unroll
        for (int e = 0; e < 4; e++) acc2[j][e] = 0.0f;

    for (int c = 0; c < NCH; c++) {
        CP_WAIT1();                    // w0(c) resident
        __syncthreads();

        // ---- GEMM1: c1[16x32 per warp] over K' = 3x192 ----
        float c1[4][4];
        #pragma unroll
        for (int j = 0; j < 4; j++)
            #pragma unroll
            for (int e = 0; e < 4; e++) c1[j][e] = 0.0f;

        #pragma unroll 1
        for (int p = 0; p < 3; p++) {
            const int aow = (p == 1) ? 96 : 0;
            const int bow = (p == 2) ? 96 : 0;
            #pragma unroll 4
            for (int kk = 0; kk < 12; kk++) {
                const int kw = kk * 8;
                const uint32_t* ap = xsw + (m0 + r) * XS_W + aow + kw + q;
                uint32_t a0 = ap[0], a1 = ap[8 * XS_W], a2 = ap[4], a3 = ap[8 * XS_W + 4];
                #pragma unroll
                for (int j = 0; j < 4; j++) {
                    const uint32_t* bp_ = w0sw + (n1 + j * 8 + r) * XS_W + bow + kw + q;
                    mma16816(c1[j], a0, a1, a2, a3, bp_[0], bp_[4]);
                }
            }
        }

        // ---- bias + relu + hi/lo split -> hs ----
        {
            const int hb = c * 64;
            #pragma unroll
            for (int j = 0; j < 4; j++) {
                int n = n1 + j * 8 + q * 2;
                float bb0 = b0s[hb + n], bb1 = b0s[hb + n + 1];
                float v0 = fmaxf(c1[j][0] + bb0, 0.f);
                float v1 = fmaxf(c1[j][1] + bb1, 0.f);
                float v2 = fmaxf(c1[j][2] + bb0, 0.f);
                float v3 = fmaxf(c1[j][3] + bb1, 0.f);
                __nv_bfloat162 h01 = __floats2bfloat162_rn(v0, v1);
                __nv_bfloat162 l01 = __floats2bfloat162_rn(v0 - __bfloat162float(h01.x),
                                                           v1 - __bfloat162float(h01.y));
                __nv_bfloat162 h23 = __floats2bfloat162_rn(v2, v3);
                __nv_bfloat162 l23 = __floats2bfloat162_rn(v2 - __bfloat162float(h23.x),
                                                           v3 - __bfloat162float(h23.y));
                int wlo = (m0 + r) * HS_W + (n >> 1);
                int whi = (m0 + r + 8) * HS_W + (n >> 1);
                hsw[wlo]      = *(uint32_t*)&h01;
                hsw[wlo + 32] = *(uint32_t*)&l01;
                hsw[whi]      = *(uint32_t*)&h23;
                hsw[whi + 32] = *(uint32_t*)&l23;
            }
        }
        __syncthreads();               // w0s free, hs complete
        if (c + 1 < NCH) load_w0(sb, c + 1, tid);

        if (c + 1 < NCH) { CP_WAIT1(); } else { CP_WAIT0(); }   // w1(c) resident
        __syncthreads();

        // ---- GEMM2: acc2 += h[64x(3x64)] @ w1 ----
        #pragma unroll 1
        for (int p = 0; p < 3; p++) {
            const int aow = (p == 1) ? 32 : 0;
            const int bow = (p == 2) ? 32 : 0;
            #pragma unroll
            for (int kk = 0; kk < 4; kk++) {
                const int kw = kk * 8;
                const uint32_t* ap = hsw + (m0 + r) * HS_W + aow + kw + q;
                uint32_t a0 = ap[0], a1 = ap[8 * HS_W], a2 = ap[4], a3 = ap[8 * HS_W + 4];
                #pragma unroll
                for (int j = 0; j < 16; j++) {
                    const uint32_t* bp_ = w1sw + (n2 + j * 8 + r) * HS_W + bow + kw + q;
                    mma16816(acc2[j], a0, a1, a2, a3, bp_[0], bp_[4]);
                }
            }
        }
        __syncthreads();               // w1s (and hs) free
        if (c + 1 < NCH) load_w1(sb, c + 1, tid);
    }

    // ---- epilogue: +b1, relu, store ----
    {
        const int rowg = slice * 128 + tokbase + m0 + r;
        #pragma unroll
        for (int j = 0; j < 16; j++) {
            int n = n2 + j * 8 + q * 2;
            float bb0 = b1s[n], bb1 = b1s[n + 1];
            float2 o0, o1;
            o0.x = fmaxf(acc2[j][0] + bb0, 0.f);
            o0.y = fmaxf(acc2[j][1] + bb1, 0.f);
            o1.x = fmaxf(acc2[j][2] + bb0, 0.f);
            o1.y = fmaxf(acc2[j][3] + bb1, 0.f);
            *(float2*)(out + (size_t)rowg * 256 + n)       = o0;
            *(float2*)(out + (size_t)(rowg + 8) * 256 + n) = o1;
        }
    }
}

extern "C" void kernel_launch(void* const* d_in, const int* in_sizes, int n_in,
                              void* d_out, int out_size)
{
    const float* x  = (const float*)d_in[0];
    const float* W0 = (const float*)d_in[1];
    const float* b0 = (const float*)d_in[2];
    const float* W1 = (const float*)d_in[3];
    const float* b1 = (const float*)d_in[4];
    float* out = (float*)d_out;

    static bool configured = false;
    if (!configured) {
        cudaFuncSetAttribute(mlp_kernel,
                             cudaFuncAttributeMaxDynamicSharedMemorySize, SM_TOTAL);
        configured = true;
    }
    prep_kernel<<<256, 256>>>(W0, W1);
    mlp_kernel<<<3072, 256, SM_TOTAL>>>(x, b0, b1, out);
}

// round 6
// speedup vs baseline: 3.0977x; 1.1794x over previous
#include <cuda_runtime.h>
#include <cuda_bf16.h>
#include <cstdint>

// Fused 2-layer MLP via mma.sync bf16 (hi/lo split, 3 products, shared frags).
//   out = relu(relu(X@W0+b0)@W1+b1); X:[196608,192] W0:[192,1024] W1:[1024,256]
// CTA: 64 rows, 256 threads (8 warps). Hidden chunked by 64.
// R5 (resubmit after infra failure): hoist hi/lo fragment loads (3 mma per
// fragment set) + 32x64 GEMM2 warp tile -> ~1.8x less shared traffic.

#define K1   192
#define HID  1024
#define EMB  256
#define NCH  16

#define XS_W  196     // words per row of Xs/W0s: 384 bf16 + pad (conflict-free: 196%32=4)
#define HS_W  68      // words per row of hs/w1s: 128 bf16 + pad (68%32=4)

// smem byte offsets (16B aligned)
#define SM_B0S 0                      // 4096
#define SM_B1S 4096                   // 1024
#define SM_XS  5120                   // 64*784  = 50176
#define SM_W0S 55296                  // 64*784  = 50176
#define SM_HS  105472                 // 64*272  = 17408
#define SM_W1S 122880                 // 256*272 = 69632
#define SM_TOTAL 192512

// Pre-split weights, [n][k] k-major, k' = [hi | lo]
__device__ __align__(16) __nv_bfloat16 g_B1[HID * 384];    // W0^T
__device__ __align__(16) __nv_bfloat16 g_B2[EMB * 2048];   // W1^T

__device__ __forceinline__ void cpa16(uint32_t dst, const void* src) {
    asm volatile("cp.async.cg.shared.global [%0], [%1], 16;" :: "r"(dst), "l"(src) : "memory");
}
#define CP_COMMIT() asm volatile("cp.async.commit_group;" ::: "memory")
#define CP_WAIT1()  asm volatile("cp.async.wait_group 1;" ::: "memory")
#define CP_WAIT0()  asm volatile("cp.async.wait_group 0;" ::: "memory")

__device__ __forceinline__ uint32_t smem_u32(const void* p) {
    uint32_t a;
    asm("{ .reg .u64 t; cvta.to.shared.u64 t, %1; cvt.u32.u64 %0, t; }" : "=r"(a) : "l"(p));
    return a;
}

__device__ __forceinline__ void mma16816(float* c,
    uint32_t a0, uint32_t a1, uint32_t a2, uint32_t a3, uint32_t b0, uint32_t b1)
{
    asm volatile("mma.sync.aligned.m16n8k16.row.col.f32.bf16.bf16.f32 "
        "{%0,%1,%2,%3}, {%4,%5,%6,%7}, {%8,%9}, {%0,%1,%2,%3};"
        : "+f"(c[0]), "+f"(c[1]), "+f"(c[2]), "+f"(c[3])
        : "r"(a0), "r"(a1), "r"(a2), "r"(a3), "r"(b0), "r"(b1));
}

// ---------------- weight prep: hi/lo split, transposed to [n][k] ----------------
__global__ void prep_kernel(const float* __restrict__ W0, const float* __restrict__ W1) {
    int stride = gridDim.x * blockDim.x;
    int t0 = blockIdx.x * blockDim.x + threadIdx.x;
    for (int i = t0; i < HID * K1; i += stride) {
        int n = i / K1, k = i % K1;
        float w = W0[k * HID + n];
        __nv_bfloat16 h = __float2bfloat16(w);
        g_B1[n * 384 + k]       = h;
        g_B1[n * 384 + 192 + k] = __float2bfloat16(w - __bfloat162float(h));
    }
    for (int i = t0; i < EMB * HID; i += stride) {
        int n = i / HID, k = i % HID;
        float w = W1[k * EMB + n];
        __nv_bfloat16 h = __float2bfloat16(w);
        g_B2[n * 2048 + k]        = h;
        g_B2[n * 2048 + 1024 + k] = __float2bfloat16(w - __bfloat162float(h));
    }
}

// ---------------- chunk loaders (cp.async) ----------------
__device__ __forceinline__ void load_w0(uint32_t sb, int c, int tid) {
    const __nv_bfloat16* base = g_B1 + (size_t)c * 64 * 384;
    #pragma unroll
    for (int i = tid; i < 3072; i += 256) {           // 64 rows x 48 x 16B
        int n = i / 48, u = i % 48;
        cpa16(sb + SM_W0S + n * 784 + u * 16, base + n * 384 + u * 8);
    }
    CP_COMMIT();
}
__device__ __forceinline__ void load_w1(uint32_t sb, int c, int tid) {
    const __nv_bfloat16* base = g_B2 + c * 64;
    #pragma unroll
    for (int i = tid; i < 4096; i += 256) {           // 256 rows x (8 hi + 8 lo) x 16B
        int n = i / 16, u = i % 16, sp = u >> 3, uu = u & 7;
        cpa16(sb + SM_W1S + n * 272 + sp * 128 + uu * 16,
              base + n * 2048 + sp * 1024 + uu * 8);
    }
    CP_COMMIT();
}

// ---------------- main fused kernel ----------------
__global__ void __launch_bounds__(256, 1)
mlp_kernel(const float* __restrict__ x, const float* __restrict__ b0,
           const float* __restrict__ b1, float* __restrict__ out)
{
    extern __shared__ char smem[];
    const uint32_t sb = smem_u32(smem);
    const int tid  = threadIdx.x;
    const int lane = tid & 31;
    const int w    = tid >> 5;
    const int r    = lane >> 2;     // fragment row 0..7
    const int q    = lane & 3;      // fragment quad col

    // GEMM1 warp tile: 16x32  (wm1 = w>>1 -> m, wn1 = w&1 -> n)
    const int m1 = (w >> 1) * 16;
    const int n1 = (w & 1) * 32;
    // GEMM2 warp tile: 32x64  (wm2 = w>>2 -> m, wn2 = w&3 -> n)
    const int m2 = (w >> 2) * 32;
    const int n2 = (w & 3) * 64;

    const int slice   = blockIdx.x >> 1;
    const int tokbase = (blockIdx.x & 1) * 64;

    uint32_t*       xsw  = (uint32_t*)(smem + SM_XS);
    const uint32_t* w0sw = (const uint32_t*)(smem + SM_W0S);
    uint32_t*       hsw  = (uint32_t*)(smem + SM_HS);
    const uint32_t* w1sw = (const uint32_t*)(smem + SM_W1S);
    float*          b0s  = (float*)(smem + SM_B0S);
    float*          b1s  = (float*)(smem + SM_B1S);

    // prefetch chunk 0 weights
    load_w0(sb, 0, tid);
    load_w1(sb, 0, tid);

    // X slice -> Xs (bf16 hi [words 0..95] || lo [96..191] per row, stride 196)
    {
        const float2* x2 = (const float2*)(x + (size_t)slice * 24576);
        #pragma unroll 4
        for (int i = tid; i < 6144; i += 256) {
            int m = i / 96, u = i % 96;
            int ch = u >> 5, bp = u & 31;
            float2 v = x2[(ch * 8192 + (tokbase + m) * 64) / 2 + bp];
            __nv_bfloat162 h2 = __floats2bfloat162_rn(v.x, v.y);
            __nv_bfloat162 l2 = __floats2bfloat162_rn(v.x - __bfloat162float(h2.x),
                                                      v.y - __bfloat162float(h2.y));
            int fw = (ch * 64) / 2 + bp;
            xsw[m * XS_W + fw]      = *(uint32_t*)&h2;
            xsw[m * XS_W + 96 + fw] = *(uint32_t*)&l2;
        }
        for (int i = tid; i < 1024; i += 256) b0s[i] = b0[i];
        for (int i = tid; i < 256;  i += 256) b1s[i] = b1[i];
    }

    float acc2[16][4];   // [j(8)][f(2)] -> acc2[j*2+f]
    #pragma unroll
    for (int j = 0; j < 16; j++)
        #pragma unroll
        for (int e = 0; e < 4; e++) acc2[j][e] = 0.0f;

    for (int c = 0; c < NCH; c++) {
        CP_WAIT1();                    // w0(c) resident
        __syncthreads();

        // ---- GEMM1: c1[16x32 per warp] over k'=3x192, shared hi/lo frags ----
        float c1[4][4];
        #pragma unroll
        for (int j = 0; j < 4; j++)
            #pragma unroll
            for (int e = 0; e < 4; e++) c1[j][e] = 0.0f;

        #pragma unroll 3
        for (int kk = 0; kk < 12; kk++) {
            const int kw = kk * 8;
            const uint32_t* ap = xsw + (m1 + r) * XS_W + kw + q;
            uint32_t ah0 = ap[0],  ah1 = ap[8 * XS_W],      ah2 = ap[4],   ah3 = ap[8 * XS_W + 4];
            uint32_t al0 = ap[96], al1 = ap[8 * XS_W + 96], al2 = ap[100], al3 = ap[8 * XS_W + 100];
            #pragma unroll
            for (int j = 0; j < 4; j++) {
                const uint32_t* bp_ = w0sw + (n1 + j * 8 + r) * XS_W + kw + q;
                uint32_t bh0 = bp_[0],  bh1 = bp_[4];
                uint32_t bl0 = bp_[96], bl1 = bp_[100];
                mma16816(c1[j], ah0, ah1, ah2, ah3, bh0, bh1);  // Ah*Bh
                mma16816(c1[j], al0, al1, al2, al3, bh0, bh1);  // Al*Bh
                mma16816(c1[j], ah0, ah1, ah2, ah3, bl0, bl1);  // Ah*Bl
            }
        }

        // ---- bias + relu + hi/lo split -> hs ----
        {
            const int hb = c * 64;
            #pragma unroll
            for (int j = 0; j < 4; j++) {
                int n = n1 + j * 8 + q * 2;
                float bb0 = b0s[hb + n], bb1 = b0s[hb + n + 1];
                float v0 = fmaxf(c1[j][0] + bb0, 0.f);
                float v1 = fmaxf(c1[j][1] + bb1, 0.f);
                float v2 = fmaxf(c1[j][2] + bb0, 0.f);
                float v3 = fmaxf(c1[j][3] + bb1, 0.f);
                __nv_bfloat162 h01 = __floats2bfloat162_rn(v0, v1);
                __nv_bfloat162 l01 = __floats2bfloat162_rn(v0 - __bfloat162float(h01.x),
                                                           v1 - __bfloat162float(h01.y));
                __nv_bfloat162 h23 = __floats2bfloat162_rn(v2, v3);
                __nv_bfloat162 l23 = __floats2bfloat162_rn(v2 - __bfloat162float(h23.x),
                                                           v3 - __bfloat162float(h23.y));
                int wlo = (m1 + r) * HS_W + (n >> 1);
                int whi = (m1 + r + 8) * HS_W + (n >> 1);
                hsw[wlo]      = *(uint32_t*)&h01;
                hsw[wlo + 32] = *(uint32_t*)&l01;
                hsw[whi]      = *(uint32_t*)&h23;
                hsw[whi + 32] = *(uint32_t*)&l23;
            }
        }
        __syncthreads();               // w0s free, hs complete
        if (c + 1 < NCH) load_w0(sb, c + 1, tid);

        if (c + 1 < NCH) { CP_WAIT1(); } else { CP_WAIT0(); }   // w1(c) resident
        __syncthreads();

        // ---- GEMM2: acc2[32x64 per warp] += h @ w1, shared hi/lo frags ----
        #pragma unroll
        for (int kk = 0; kk < 4; kk++) {
            const int kw = kk * 8;
            uint32_t ah[2][4], al[2][4];
            #pragma unroll
            for (int f = 0; f < 2; f++) {
                const uint32_t* ap = hsw + (m2 + f * 16 + r) * HS_W + kw + q;
                ah[f][0] = ap[0];  ah[f][1] = ap[8 * HS_W];      ah[f][2] = ap[4];  ah[f][3] = ap[8 * HS_W + 4];
                al[f][0] = ap[32]; al[f][1] = ap[8 * HS_W + 32]; al[f][2] = ap[36]; al[f][3] = ap[8 * HS_W + 36];
            }
            #pragma unroll
            for (int j = 0; j < 8; j++) {
                const uint32_t* bp_ = w1sw + (n2 + j * 8 + r) * HS_W + kw + q;
                uint32_t bh0 = bp_[0],  bh1 = bp_[4];
                uint32_t bl0 = bp_[32], bl1 = bp_[36];
                #pragma unroll
                for (int f = 0; f < 2; f++) {
                    mma16816(acc2[j * 2 + f], ah[f][0], ah[f][1], ah[f][2], ah[f][3], bh0, bh1);
                    mma16816(acc2[j * 2 + f], al[f][0], al[f][1], al[f][2], al[f][3], bh0, bh1);
                    mma16816(acc2[j * 2 + f], ah[f][0], ah[f][1], ah[f][2], ah[f][3], bl0, bl1);
                }
            }
        }
        __syncthreads();               // w1s (and hs) free
        if (c + 1 < NCH) load_w1(sb, c + 1, tid);
    }

    // ---- epilogue: +b1, relu, store ----
    {
        #pragma unroll
        for (int j = 0; j < 8; j++) {
            int n = n2 + j * 8 + q * 2;
            float bb0 = b1s[n], bb1 = b1s[n + 1];
            #pragma unroll
            for (int f = 0; f < 2; f++) {
                const int rowg = slice * 128 + tokbase + m2 + f * 16 + r;
                float2 o0, o1;
                o0.x = fmaxf(acc2[j * 2 + f][0] + bb0, 0.f);
                o0.y = fmaxf(acc2[j * 2 + f][1] + bb1, 0.f);
                o1.x = fmaxf(acc2[j * 2 + f][2] + bb0, 0.f);
                o1.y = fmaxf(acc2[j * 2 + f][3] + bb1, 0.f);
                *(float2*)(out + (size_t)rowg * 256 + n)       = o0;
                *(float2*)(out + (size_t)(rowg + 8) * 256 + n) = o1;
            }
        }
    }
}

extern "C" void kernel_launch(void* const* d_in, const int* in_sizes, int n_in,
                              void* d_out, int out_size)
{
    const float* x  = (const float*)d_in[0];
    const float* W0 = (const float*)d_in[1];
    const float* b0 = (const float*)d_in[2];
    const float* W1 = (const float*)d_in[3];
    const float* b1 = (const float*)d_in[4];
    float* out = (float*)d_out;

    static bool configured = false;
    if (!configured) {
        cudaFuncSetAttribute(mlp_kernel,
                             cudaFuncAttributeMaxDynamicSharedMemorySize, SM_TOTAL);
        configured = true;
    }
    prep_kernel<<<256, 256>>>(W0, W1);
    mlp_kernel<<<3072, 256, SM_TOTAL>>>(x, b0, b1, out);
}

// round 7
// speedup vs baseline: 3.2574x; 1.0516x over previous
#include <cuda_runtime.h>
#include <cuda_bf16.h>
#include <cstdint>

// Fused 2-layer MLP, mma.sync bf16 hi/lo split (3 products), warp-specialized:
//   warps 0-7  (group A): GEMM1 producer -> h chunks into double-buffered hs
//   warps 8-15 (group B): GEMM2 consumer -> out accumulators
// Cross-group sync via named bar.arrive/bar.sync; weights staged per-group
// with cp.async. X resident in smem (bf16 hi/lo) for the whole CTA.

#define K1   192
#define HID  1024
#define EMB  256
#define NCH  16

#define XS_W  196     // words per row of Xs/W0s (384 bf16 + pad; 196%32=4 -> conflict-free)
#define HS_W  68      // words per row of hs/w1s (128 bf16 + pad)

// smem byte offsets
#define SM_B0S 0                      // 4096
#define SM_B1S 4096                   // 1024
#define SM_XS  5120                   // 64*784  = 50176
#define SM_W0S 55296                  // 64*784  = 50176
#define SM_HS  105472                 // 2 x 64*272 = 34816 (double-buffered)
#define SM_W1S 140288                 // 256*272 = 69632
#define SM_TOTAL 209920

// named barriers
#define BFULL(p) (1 + (p))   // A arrives (hs[p] full), B syncs
#define BFREE(p) (3 + (p))   // B arrives (hs[p] free), A syncs
#define BINTA 5              // intra group A (256 thr)
#define BINTB 6              // intra group B (256 thr)

#define BAR_SYNC(id, n)   asm volatile("bar.sync %0, %1;"   :: "r"(id), "r"(n) : "memory")
#define BAR_ARRIVE(id, n) asm volatile("bar.arrive %0, %1;" :: "r"(id), "r"(n) : "memory")

// Pre-split weights, [n][k] k-major, k' = [hi | lo]
__device__ __align__(16) __nv_bfloat16 g_B1[HID * 384];    // W0^T
__device__ __align__(16) __nv_bfloat16 g_B2[EMB * 2048];   // W1^T

__device__ __forceinline__ void cpa16(uint32_t dst, const void* src) {
    asm volatile("cp.async.cg.shared.global [%0], [%1], 16;" :: "r"(dst), "l"(src) : "memory");
}
#define CP_COMMIT() asm volatile("cp.async.commit_group;" ::: "memory")
#define CP_WAIT0()  asm volatile("cp.async.wait_group 0;" ::: "memory")

__device__ __forceinline__ uint32_t smem_u32(const void* p) {
    uint32_t a;
    asm("{ .reg .u64 t; cvta.to.shared.u64 t, %1; cvt.u32.u64 %0, t; }" : "=r"(a) : "l"(p));
    return a;
}

__device__ __forceinline__ void mma16816(float* c,
    uint32_t a0, uint32_t a1, uint32_t a2, uint32_t a3, uint32_t b0, uint32_t b1)
{
    asm volatile("mma.sync.aligned.m16n8k16.row.col.f32.bf16.bf16.f32 "
        "{%0,%1,%2,%3}, {%4,%5,%6,%7}, {%8,%9}, {%0,%1,%2,%3};"
        : "+f"(c[0]), "+f"(c[1]), "+f"(c[2]), "+f"(c[3])
        : "r"(a0), "r"(a1), "r"(a2), "r"(a3), "r"(b0), "r"(b1));
}

// ---------------- weight prep: hi/lo split, transposed to [n][k] ----------------
__global__ void prep_kernel(const float* __restrict__ W0, const float* __restrict__ W1) {
    int stride = gridDim.x * blockDim.x;
    int t0 = blockIdx.x * blockDim.x + threadIdx.x;
    for (int i = t0; i < HID * K1; i += stride) {
        int n = i / K1, k = i % K1;
        float w = W0[k * HID + n];
        __nv_bfloat16 h = __float2bfloat16(w);
        g_B1[n * 384 + k]       = h;
        g_B1[n * 384 + 192 + k] = __float2bfloat16(w - __bfloat162float(h));
    }
    for (int i = t0; i < EMB * HID; i += stride) {
        int n = i / HID, k = i % HID;
        float w = W1[k * EMB + n];
        __nv_bfloat16 h = __float2bfloat16(w);
        g_B2[n * 2048 + k]        = h;
        g_B2[n * 2048 + 1024 + k] = __float2bfloat16(w - __bfloat162float(h));
    }
}

// ---------------- per-group chunk loaders (256 threads each) ----------------
__device__ __forceinline__ void load_w0(uint32_t sb, int c, int gtid) {
    const __nv_bfloat16* base = g_B1 + (size_t)c * 64 * 384;
    #pragma unroll
    for (int i = gtid; i < 3072; i += 256) {          // 64 rows x 48 x 16B
        int n = i / 48, u = i % 48;
        cpa16(sb + SM_W0S + n * 784 + u * 16, base + n * 384 + u * 8);
    }
    CP_COMMIT();
}
__device__ __forceinline__ void load_w1(uint32_t sb, int c, int gtid) {
    const __nv_bfloat16* base = g_B2 + c * 64;
    #pragma unroll
    for (int i = gtid; i < 4096; i += 256) {          // 256 rows x (8 hi + 8 lo) x 16B
        int n = i / 16, u = i % 16, sp = u >> 3, uu = u & 7;
        cpa16(sb + SM_W1S + n * 272 + sp * 128 + uu * 16,
              base + n * 2048 + sp * 1024 + uu * 8);
    }
    CP_COMMIT();
}

// ---------------- main fused kernel ----------------
__global__ void __launch_bounds__(512, 1)
mlp_kernel(const float* __restrict__ x, const float* __restrict__ b0,
           const float* __restrict__ b1, float* __restrict__ out)
{
    extern __shared__ char smem[];
    const uint32_t sb = smem_u32(smem);
    const int tid  = threadIdx.x;
    const int lane = tid & 31;
    const int w    = tid >> 5;
    const int gtid = tid & 255;       // tid within group
    const int r    = lane >> 2;
    const int q    = lane & 3;
    const bool isA = (w < 8);

    const int slice   = blockIdx.x >> 1;
    const int tokbase = (blockIdx.x & 1) * 64;

    uint32_t*       xsw  = (uint32_t*)(smem + SM_XS);
    const uint32_t* w0sw = (const uint32_t*)(smem + SM_W0S);
    uint32_t*       hsw  = (uint32_t*)(smem + SM_HS);
    const uint32_t* w1sw = (const uint32_t*)(smem + SM_W1S);
    float*          b0s  = (float*)(smem + SM_B0S);
    float*          b1s  = (float*)(smem + SM_B1S);

    // group-owned prefetch of chunk 0 weights
    if (isA) load_w0(sb, 0, gtid);
    else     load_w1(sb, 0, gtid);

    // X slice -> Xs (bf16 hi [words 0..95] || lo [96..191] per row, stride 196)
    {
        const float2* x2 = (const float2*)(x + (size_t)slice * 24576);
        #pragma unroll 4
        for (int i = tid; i < 6144; i += 512) {
            int m = i / 96, u = i % 96;
            int ch = u >> 5, bp = u & 31;
            float2 v = x2[(ch * 8192 + (tokbase + m) * 64) / 2 + bp];
            __nv_bfloat162 h2 = __floats2bfloat162_rn(v.x, v.y);
            __nv_bfloat162 l2 = __floats2bfloat162_rn(v.x - __bfloat162float(h2.x),
                                                      v.y - __bfloat162float(h2.y));
            int fw = (ch * 64) / 2 + bp;
            xsw[m * XS_W + fw]      = *(uint32_t*)&h2;
            xsw[m * XS_W + 96 + fw] = *(uint32_t*)&l2;
        }
        for (int i = tid; i < 1024; i += 512) b0s[i] = b0[i];
        for (int i = tid; i < 256;  i += 512) b1s[i] = b1[i];
    }
    __syncthreads();      // X, biases staged; groups diverge from here

    if (isA) {
        // ================= group A: GEMM1 producer =================
        const int m1 = (w >> 1) * 16;
        const int n1 = (w & 1) * 32;

        for (int c = 0; c < NCH; c++) {
            const int p = c & 1;
            CP_WAIT0();                 // this thread's w0(c) parts done
            BAR_SYNC(BINTA, 256);       // w0s visible to all of A

            float c1[4][4];
            #pragma unroll
            for (int j = 0; j < 4; j++)
                #pragma unroll
                for (int e = 0; e < 4; e++) c1[j][e] = 0.0f;

            #pragma unroll 3
            for (int kk = 0; kk < 12; kk++) {
                const int kw = kk * 8;
                const uint32_t* ap = xsw + (m1 + r) * XS_W + kw + q;
                uint32_t ah0 = ap[0],  ah1 = ap[8 * XS_W],      ah2 = ap[4],   ah3 = ap[8 * XS_W + 4];
                uint32_t al0 = ap[96], al1 = ap[8 * XS_W + 96], al2 = ap[100], al3 = ap[8 * XS_W + 100];
                #pragma unroll
                for (int j = 0; j < 4; j++) {
                    const uint32_t* bp_ = w0sw + (n1 + j * 8 + r) * XS_W + kw + q;
                    uint32_t bh0 = bp_[0],  bh1 = bp_[4];
                    uint32_t bl0 = bp_[96], bl1 = bp_[100];
                    mma16816(c1[j], ah0, ah1, ah2, ah3, bh0, bh1);
                    mma16816(c1[j], al0, al1, al2, al3, bh0, bh1);
                    mma16816(c1[j], ah0, ah1, ah2, ah3, bl0, bl1);
                }
            }
            BAR_SYNC(BINTA, 256);       // all A done reading w0s
            if (c + 1 < NCH) load_w0(sb, c + 1, gtid);

            if (c >= 2) BAR_SYNC(BFREE(p), 512);   // hs[p] free (B finished c-2)

            // bias + relu + hi/lo split -> hs[p]
            {
                uint32_t* hsp = hsw + p * 4352;
                const int hb = c * 64;
                #pragma unroll
                for (int j = 0; j < 4; j++) {
                    int n = n1 + j * 8 + q * 2;
                    float bb0 = b0s[hb + n], bb1 = b0s[hb + n + 1];
                    float v0 = fmaxf(c1[j][0] + bb0, 0.f);
                    float v1 = fmaxf(c1[j][1] + bb1, 0.f);
                    float v2 = fmaxf(c1[j][2] + bb0, 0.f);
                    float v3 = fmaxf(c1[j][3] + bb1, 0.f);
                    __nv_bfloat162 h01 = __floats2bfloat162_rn(v0, v1);
                    __nv_bfloat162 l01 = __floats2bfloat162_rn(v0 - __bfloat162float(h01.x),
                                                               v1 - __bfloat162float(h01.y));
                    __nv_bfloat162 h23 = __floats2bfloat162_rn(v2, v3);
                    __nv_bfloat162 l23 = __floats2bfloat162_rn(v2 - __bfloat162float(h23.x),
                                                               v3 - __bfloat162float(h23.y));
                    int wlo = (m1 + r) * HS_W + (n >> 1);
                    int whi = (m1 + r + 8) * HS_W + (n >> 1);
                    hsp[wlo]      = *(uint32_t*)&h01;
                    hsp[wlo + 32] = *(uint32_t*)&l01;
                    hsp[whi]      = *(uint32_t*)&h23;
                    hsp[whi + 32] = *(uint32_t*)&l23;
                }
            }
            BAR_ARRIVE(BFULL(p), 512);  // hs[p] published to B
        }
        // group A exits (all arrivals already posted)
    } else {
        // ================= group B: GEMM2 consumer =================
        const int wB = w - 8;
        const int m2 = (wB >> 2) * 32;
        const int n2 = (wB & 3) * 64;

        float acc2[16][4];
        #pragma unroll
        for (int j = 0; j < 16; j++)
            #pragma unroll
            for (int e = 0; e < 4; e++) acc2[j][e] = 0.0f;

        for (int c = 0; c < NCH; c++) {
            const int p = c & 1;
            CP_WAIT0();                 // this thread's w1(c) parts done
            BAR_SYNC(BINTB, 256);       // w1s visible to all of B
            BAR_SYNC(BFULL(p), 512);    // hs[p] ready

            const uint32_t* hsp = hsw + p * 4352;
            #pragma unroll
            for (int kk = 0; kk < 4; kk++) {
                const int kw = kk * 8;
                uint32_t ah[2][4], al[2][4];
                #pragma unroll
                for (int f = 0; f < 2; f++) {
                    const uint32_t* ap = hsp + (m2 + f * 16 + r) * HS_W + kw + q;
                    ah[f][0] = ap[0];  ah[f][1] = ap[8 * HS_W];      ah[f][2] = ap[4];  ah[f][3] = ap[8 * HS_W + 4];
                    al[f][0] = ap[32]; al[f][1] = ap[8 * HS_W + 32]; al[f][2] = ap[36]; al[f][3] = ap[8 * HS_W + 36];
                }
                #pragma unroll
                for (int j = 0; j < 8; j++) {
                    const uint32_t* bp_ = w1sw + (n2 + j * 8 + r) * HS_W + kw + q;
                    uint32_t bh0 = bp_[0],  bh1 = bp_[4];
                    uint32_t bl0 = bp_[32], bl1 = bp_[36];
                    #pragma unroll
                    for (int f = 0; f < 2; f++) {
                        mma16816(acc2[j * 2 + f], ah[f][0], ah[f][1], ah[f][2], ah[f][3], bh0, bh1);
                        mma16816(acc2[j * 2 + f], al[f][0], al[f][1], al[f][2], al[f][3], bh0, bh1);
                        mma16816(acc2[j * 2 + f], ah[f][0], ah[f][1], ah[f][2], ah[f][3], bl0, bl1);
                    }
                }
            }
            BAR_SYNC(BINTB, 256);       // all B done reading w1s + hs[p]
            if (c + 1 < NCH) load_w1(sb, c + 1, gtid);
            if (c + 2 < NCH) BAR_ARRIVE(BFREE(p), 512);   // hs[p] reusable by A
        }

        // ---- epilogue: +b1, relu, store ----
        #pragma unroll
        for (int j = 0; j < 8; j++) {
            int n = n2 + j * 8 + q * 2;
            float bb0 = b1s[n], bb1 = b1s[n + 1];
            #pragma unroll
            for (int f = 0; f < 2; f++) {
                const int rowg = slice * 128 + tokbase + m2 + f * 16 + r;
                float2 o0, o1;
                o0.x = fmaxf(acc2[j * 2 + f][0] + bb0, 0.f);
                o0.y = fmaxf(acc2[j * 2 + f][1] + bb1, 0.f);
                o1.x = fmaxf(acc2[j * 2 + f][2] + bb0, 0.f);
                o1.y = fmaxf(acc2[j * 2 + f][3] + bb1, 0.f);
                *(float2*)(out + (size_t)rowg * 256 + n)       = o0;
                *(float2*)(out + (size_t)(rowg + 8) * 256 + n) = o1;
            }
        }
    }
}

extern "C" void kernel_launch(void* const* d_in, const int* in_sizes, int n_in,
                              void* d_out, int out_size)
{
    const float* x  = (const float*)d_in[0];
    const float* W0 = (const float*)d_in[1];
    const float* b0 = (const float*)d_in[2];
    const float* W1 = (const float*)d_in[3];
    const float* b1 = (const float*)d_in[4];
    float* out = (float*)d_out;

    static bool configured = false;
    if (!configured) {
        cudaFuncSetAttribute(mlp_kernel,
                             cudaFuncAttributeMaxDynamicSharedMemorySize, SM_TOTAL);
        configured = true;
    }
    prep_kernel<<<256, 256>>>(W0, W1);
    mlp_kernel<<<3072, 512, SM_TOTAL>>>(x, b0, b1, out);
}

// round 8
// speedup vs baseline: 4.7034x; 1.4439x over previous
#include <cuda_runtime.h>
#include <cuda_fp16.h>
#include <cstdint>

// Fused 2-layer MLP, mma.sync fp16, activation hi/lo split (2 products):
//   A = Ah + Al (fp16 split of X / h)  ->  Ah*B + Al*B = A*B exactly;
//   only weight fp16 rounding (~2^-12) is uncompensated.
// Warp-specialized: warps 0-7 (A) = GEMM1 producer, warps 8-15 (B) = GEMM2
// consumer, double-buffered hs, named barriers, cp.async weight staging.

#define K1   192
#define HID  1024
#define EMB  256
#define NCH  16

#define XS_W  196     // words/row Xs: 192 hi + 192 lo fp16 + pad (196%32=4)
#define W0S_W 100     // words/row w0s: 192 fp16 + pad (100%32=4)
#define HS_W  68      // words/row hs: 64 hi + 64 lo fp16 + pad (68%32=4)
#define W1S_W 36      // words/row w1s: 64 fp16 + pad (36%32=4)

// smem byte offsets
#define SM_B0S 0                      // 4096
#define SM_B1S 4096                   // 1024
#define SM_XS  5120                   // 64*784  = 50176
#define SM_W0S 55296                  // 64*400  = 25600
#define SM_HS  80896                  // 2 x 64*272 = 34816
#define SM_W1S 115712                 // 256*144 = 36864
#define SM_TOTAL 152576

// named barriers
#define BFULL(p) (1 + (p))
#define BFREE(p) (3 + (p))
#define BINTA 5
#define BINTB 6

#define BAR_SYNC(id, n)   asm volatile("bar.sync %0, %1;"   :: "r"(id), "r"(n) : "memory")
#define BAR_ARRIVE(id, n) asm volatile("bar.arrive %0, %1;" :: "r"(id), "r"(n) : "memory")

// Pre-transposed fp16 weights, [n][k] k-major
__device__ __align__(16) __half g_B1[HID * K1];     // W0^T
__device__ __align__(16) __half g_B2[EMB * HID];    // W1^T

__device__ __forceinline__ void cpa16(uint32_t dst, const void* src) {
    asm volatile("cp.async.cg.shared.global [%0], [%1], 16;" :: "r"(dst), "l"(src) : "memory");
}
#define CP_COMMIT() asm volatile("cp.async.commit_group;" ::: "memory")
#define CP_WAIT0()  asm volatile("cp.async.wait_group 0;" ::: "memory")

__device__ __forceinline__ uint32_t smem_u32(const void* p) {
    uint32_t a;
    asm("{ .reg .u64 t; cvta.to.shared.u64 t, %1; cvt.u32.u64 %0, t; }" : "=r"(a) : "l"(p));
    return a;
}

__device__ __forceinline__ void mma16816(float* c,
    uint32_t a0, uint32_t a1, uint32_t a2, uint32_t a3, uint32_t b0, uint32_t b1)
{
    asm volatile("mma.sync.aligned.m16n8k16.row.col.f32.f16.f16.f32 "
        "{%0,%1,%2,%3}, {%4,%5,%6,%7}, {%8,%9}, {%0,%1,%2,%3};"
        : "+f"(c[0]), "+f"(c[1]), "+f"(c[2]), "+f"(c[3])
        : "r"(a0), "r"(a1), "r"(a2), "r"(a3), "r"(b0), "r"(b1));
}

__device__ __forceinline__ uint32_t pack2(float x, float y) {
    __half2 h = __halves2half2(__float2half_rn(x), __float2half_rn(y));
    return *(uint32_t*)&h;
}
__device__ __forceinline__ uint32_t pack2lo(float x, float y, uint32_t hw) {
    __half2 h = *(__half2*)&hw;
    return pack2(x - __half2float(__low2half(h)), y - __half2float(__high2half(h)));
}

// ---------------- weight prep: fp16, transposed to [n][k] ----------------
__global__ void prep_kernel(const float* __restrict__ W0, const float* __restrict__ W1) {
    int stride = gridDim.x * blockDim.x;
    int t0 = blockIdx.x * blockDim.x + threadIdx.x;
    for (int i = t0; i < HID * K1; i += stride) {
        int n = i / K1, k = i % K1;
        g_B1[n * K1 + k] = __float2half_rn(W0[k * HID + n]);
    }
    for (int i = t0; i < EMB * HID; i += stride) {
        int n = i / HID, k = i % HID;
        g_B2[n * HID + k] = __float2half_rn(W1[k * EMB + n]);
    }
}

// ---------------- per-group chunk loaders (256 threads each) ----------------
__device__ __forceinline__ void load_w0(uint32_t sb, int c, int gtid) {
    const __half* base = g_B1 + (size_t)c * 64 * K1;
    #pragma unroll
    for (int i = gtid; i < 1536; i += 256) {          // 64 rows x 24 x 16B
        int n = i / 24, u = i % 24;
        cpa16(sb + SM_W0S + n * 400 + u * 16, base + n * K1 + u * 8);
    }
    CP_COMMIT();
}
__device__ __forceinline__ void load_w1(uint32_t sb, int c, int gtid) {
    const __half* base = g_B2 + c * 64;
    #pragma unroll
    for (int i = gtid; i < 2048; i += 256) {          // 256 rows x 8 x 16B
        int n = i / 8, u = i % 8;
        cpa16(sb + SM_W1S + n * 144 + u * 16, base + n * HID + u * 8);
    }
    CP_COMMIT();
}

// ---------------- main fused kernel ----------------
__global__ void __launch_bounds__(512, 1)
mlp_kernel(const float* __restrict__ x, const float* __restrict__ b0,
           const float* __restrict__ b1, float* __restrict__ out)
{
    extern __shared__ char smem[];
    const uint32_t sb = smem_u32(smem);
    const int tid  = threadIdx.x;
    const int lane = tid & 31;
    const int w    = tid >> 5;
    const int gtid = tid & 255;
    const int r    = lane >> 2;
    const int q    = lane & 3;
    const bool isA = (w < 8);

    const int slice   = blockIdx.x >> 1;
    const int tokbase = (blockIdx.x & 1) * 64;

    uint32_t*       xsw  = (uint32_t*)(smem + SM_XS);
    const uint32_t* w0sw = (const uint32_t*)(smem + SM_W0S);
    uint32_t*       hsw  = (uint32_t*)(smem + SM_HS);
    const uint32_t* w1sw = (const uint32_t*)(smem + SM_W1S);
    float*          b0s  = (float*)(smem + SM_B0S);
    float*          b1s  = (float*)(smem + SM_B1S);

    if (isA) load_w0(sb, 0, gtid);
    else     load_w1(sb, 0, gtid);

    // X slice -> Xs (fp16 hi [words 0..95] || lo [96..191] per row)
    {
        const float2* x2 = (const float2*)(x + (size_t)slice * 24576);
        #pragma unroll 4
        for (int i = tid; i < 6144; i += 512) {
            int m = i / 96, u = i % 96;
            int ch = u >> 5, bp = u & 31;
            float2 v = x2[(ch * 8192 + (tokbase + m) * 64) / 2 + bp];
            uint32_t hw = pack2(v.x, v.y);
            uint32_t lw = pack2lo(v.x, v.y, hw);
            int fw = (ch * 64) / 2 + bp;
            xsw[m * XS_W + fw]      = hw;
            xsw[m * XS_W + 96 + fw] = lw;
        }
        for (int i = tid; i < 1024; i += 512) b0s[i] = b0[i];
        for (int i = tid; i < 256;  i += 512) b1s[i] = b1[i];
    }
    __syncthreads();

    if (isA) {
        // ================= group A: GEMM1 producer =================
        const int m1 = (w >> 1) * 16;
        const int n1 = (w & 1) * 32;

        for (int c = 0; c < NCH; c++) {
            const int p = c & 1;
            CP_WAIT0();
            BAR_SYNC(BINTA, 256);

            float c1[4][4];
            #pragma unroll
            for (int j = 0; j < 4; j++)
                #pragma unroll
                for (int e = 0; e < 4; e++) c1[j][e] = 0.0f;

            #pragma unroll 3
            for (int kk = 0; kk < 12; kk++) {
                const int kw = kk * 8;
                const uint32_t* ap = xsw + (m1 + r) * XS_W + kw + q;
                uint32_t ah0 = ap[0],  ah1 = ap[8 * XS_W],      ah2 = ap[4],   ah3 = ap[8 * XS_W + 4];
                uint32_t al0 = ap[96], al1 = ap[8 * XS_W + 96], al2 = ap[100], al3 = ap[8 * XS_W + 100];
                #pragma unroll
                for (int j = 0; j < 4; j++) {
                    const uint32_t* bp_ = w0sw + (n1 + j * 8 + r) * W0S_W + kw + q;
                    uint32_t bh0 = bp_[0], bh1 = bp_[4];
                    mma16816(c1[j], ah0, ah1, ah2, ah3, bh0, bh1);   // Ah*B
                    mma16816(c1[j], al0, al1, al2, al3, bh0, bh1);   // Al*B
                }
            }
            BAR_SYNC(BINTA, 256);
            if (c + 1 < NCH) load_w0(sb, c + 1, gtid);

            if (c >= 2) BAR_SYNC(BFREE(p), 512);

            // bias + relu + fp16 hi/lo split -> hs[p]
            {
                uint32_t* hsp = hsw + p * 4352;
                const int hb = c * 64;
                #pragma unroll
                for (int j = 0; j < 4; j++) {
                    int n = n1 + j * 8 + q * 2;
                    float bb0 = b0s[hb + n], bb1 = b0s[hb + n + 1];
                    float v0 = fmaxf(c1[j][0] + bb0, 0.f);
                    float v1 = fmaxf(c1[j][1] + bb1, 0.f);
                    float v2 = fmaxf(c1[j][2] + bb0, 0.f);
                    float v3 = fmaxf(c1[j][3] + bb1, 0.f);
                    uint32_t h01 = pack2(v0, v1), l01 = pack2lo(v0, v1, h01);
                    uint32_t h23 = pack2(v2, v3), l23 = pack2lo(v2, v3, h23);
                    int wlo = (m1 + r) * HS_W + (n >> 1);
                    int whi = (m1 + r + 8) * HS_W + (n >> 1);
                    hsp[wlo]      = h01;
                    hsp[wlo + 32] = l01;
                    hsp[whi]      = h23;
                    hsp[whi + 32] = l23;
                }
            }
            BAR_ARRIVE(BFULL(p), 512);
        }
    } else {
        // ================= group B: GEMM2 consumer =================
        const int wB = w - 8;
        const int m2 = (wB >> 2) * 32;
        const int n2 = (wB & 3) * 64;

        float acc2[16][4];
        #pragma unroll
        for (int j = 0; j < 16; j++)
            #pragma unroll
            for (int e = 0; e < 4; e++) acc2[j][e] = 0.0f;

        for (int c = 0; c < NCH; c++) {
            const int p = c & 1;
            CP_WAIT0();
            BAR_SYNC(BINTB, 256);
            BAR_SYNC(BFULL(p), 512);

            const uint32_t* hsp = hsw + p * 4352;
            #pragma unroll
            for (int kk = 0; kk < 4; kk++) {
                const int kw = kk * 8;
                uint32_t ah[2][4], al[2][4];
                #pragma unroll
                for (int f = 0; f < 2; f++) {
                    const uint32_t* ap = hsp + (m2 + f * 16 + r) * HS_W + kw + q;
                    ah[f][0] = ap[0];  ah[f][1] = ap[8 * HS_W];      ah[f][2] = ap[4];  ah[f][3] = ap[8 * HS_W + 4];
                    al[f][0] = ap[32]; al[f][1] = ap[8 * HS_W + 32]; al[f][2] = ap[36]; al[f][3] = ap[8 * HS_W + 36];
                }
                #pragma unroll
                for (int j = 0; j < 8; j++) {
                    const uint32_t* bp_ = w1sw + (n2 + j * 8 + r) * W1S_W + kw + q;
                    uint32_t bh0 = bp_[0], bh1 = bp_[4];
                    #pragma unroll
                    for (int f = 0; f < 2; f++) {
                        mma16816(acc2[j * 2 + f], ah[f][0], ah[f][1], ah[f][2], ah[f][3], bh0, bh1);
                        mma16816(acc2[j * 2 + f], al[f][0], al[f][1], al[f][2], al[f][3], bh0, bh1);
                    }
                }
            }
            BAR_SYNC(BINTB, 256);
            if (c + 1 < NCH) load_w1(sb, c + 1, gtid);
            if (c + 2 < NCH) BAR_ARRIVE(BFREE(p), 512);
        }

        // ---- epilogue: +b1, relu, store ----
        #pragma unroll
        for (int j = 0; j < 8; j++) {
            int n = n2 + j * 8 + q * 2;
            float bb0 = b1s[n], bb1 = b1s[n + 1];
            #pragma unroll
            for (int f = 0; f < 2; f++) {
                const int rowg = slice * 128 + tokbase + m2 + f * 16 + r;
                float2 o0, o1;
                o0.x = fmaxf(acc2[j * 2 + f][0] + bb0, 0.f);
                o0.y = fmaxf(acc2[j * 2 + f][1] + bb1, 0.f);
                o1.x = fmaxf(acc2[j * 2 + f][2] + bb0, 0.f);
                o1.y = fmaxf(acc2[j * 2 + f][3] + bb1, 0.f);
                *(float2*)(out + (size_t)rowg * 256 + n)       = o0;
                *(float2*)(out + (size_t)(rowg + 8) * 256 + n) = o1;
            }
        }
    }
}

extern "C" void kernel_launch(void* const* d_in, const int* in_sizes, int n_in,
                              void* d_out, int out_size)
{
    const float* x  = (const float*)d_in[0];
    const float* W0 = (const float*)d_in[1];
    const float* b0 = (const float*)d_in[2];
    const float* W1 = (const float*)d_in[3];
    const float* b1 = (const float*)d_in[4];
    float* out = (float*)d_out;

    static bool configured = false;
    if (!configured) {
        cudaFuncSetAttribute(mlp_kernel,
                             cudaFuncAttributeMaxDynamicSharedMemorySize, SM_TOTAL);
        configured = true;
    }
    prep_kernel<<<256, 256>>>(W0, W1);
    mlp_kernel<<<3072, 512, SM_TOTAL>>>(x, b0, b1, out);
}

// round 9
// speedup vs baseline: 6.7904x; 1.4437x over previous
#include <cuda_runtime.h>
#include <cuda_fp16.h>
#include <cstdint>

// Fused 2-layer MLP, pure fp16 mma.sync (no hi/lo compensation):
//   out = relu(relu(X@W0+b0)@W1+b1)
// Error model (validated R8): each fp16 rounding source ~1.4-2e-4 RMS rel,
// adding in quadrature -> predicted ~3.5-5e-4 < 1e-3 gate.
// Warp-specialized: warps 0-7 = GEMM1 producer, warps 8-15 = GEMM2 consumer,
// double-buffered hs, named barriers, cp.async weight staging.

#define K1   192
#define HID  1024
#define EMB  256
#define NCH  16

#define XS_W  100     // words/row Xs: 192 fp16 = 96 w + 4 pad (100%32=4 -> conflict-free)
#define W0S_W 100     // words/row w0s: 192 fp16 + pad
#define HS_W  36      // words/row hs: 64 fp16 = 32 w + 4 pad (36%32=4)
#define W1S_W 36      // words/row w1s: 64 fp16 + pad

// smem byte offsets
#define SM_B0S 0                      // 4096
#define SM_B1S 4096                   // 1024
#define SM_XS  5120                   // 64*400  = 25600
#define SM_W0S 30720                  // 64*400  = 25600
#define SM_HS  56320                  // 2 x 64*144 = 18432
#define SM_W1S 74752                  // 256*144 = 36864
#define SM_TOTAL 111616

// named barriers
#define BFULL(p) (1 + (p))
#define BFREE(p) (3 + (p))
#define BINTA 5
#define BINTB 6

#define BAR_SYNC(id, n)   asm volatile("bar.sync %0, %1;"   :: "r"(id), "r"(n) : "memory")
#define BAR_ARRIVE(id, n) asm volatile("bar.arrive %0, %1;" :: "r"(id), "r"(n) : "memory")

// Pre-transposed fp16 weights, [n][k] k-major
__device__ __align__(16) __half g_B1[HID * K1];     // W0^T
__device__ __align__(16) __half g_B2[EMB * HID];    // W1^T

__device__ __forceinline__ void cpa16(uint32_t dst, const void* src) {
    asm volatile("cp.async.cg.shared.global [%0], [%1], 16;" :: "r"(dst), "l"(src) : "memory");
}
#define CP_COMMIT() asm volatile("cp.async.commit_group;" ::: "memory")
#define CP_WAIT0()  asm volatile("cp.async.wait_group 0;" ::: "memory")

__device__ __forceinline__ uint32_t smem_u32(const void* p) {
    uint32_t a;
    asm("{ .reg .u64 t; cvta.to.shared.u64 t, %1; cvt.u32.u64 %0, t; }" : "=r"(a) : "l"(p));
    return a;
}

__device__ __forceinline__ void mma16816(float* c,
    uint32_t a0, uint32_t a1, uint32_t a2, uint32_t a3, uint32_t b0, uint32_t b1)
{
    asm volatile("mma.sync.aligned.m16n8k16.row.col.f32.f16.f16.f32 "
        "{%0,%1,%2,%3}, {%4,%5,%6,%7}, {%8,%9}, {%0,%1,%2,%3};"
        : "+f"(c[0]), "+f"(c[1]), "+f"(c[2]), "+f"(c[3])
        : "r"(a0), "r"(a1), "r"(a2), "r"(a3), "r"(b0), "r"(b1));
}

__device__ __forceinline__ uint32_t pack2(float x, float y) {
    __half2 h = __halves2half2(__float2half_rn(x), __float2half_rn(y));
    return *(uint32_t*)&h;
}

// ---------------- weight prep: fp16, transposed to [n][k] ----------------
__global__ void prep_kernel(const float* __restrict__ W0, const float* __restrict__ W1) {
    int stride = gridDim.x * blockDim.x;
    int t0 = blockIdx.x * blockDim.x + threadIdx.x;
    for (int i = t0; i < HID * K1; i += stride) {
        int n = i / K1, k = i % K1;
        g_B1[n * K1 + k] = __float2half_rn(W0[k * HID + n]);
    }
    for (int i = t0; i < EMB * HID; i += stride) {
        int n = i / HID, k = i % HID;
        g_B2[n * HID + k] = __float2half_rn(W1[k * EMB + n]);
    }
}

// ---------------- per-group chunk loaders (256 threads each) ----------------
__device__ __forceinline__ void load_w0(uint32_t sb, int c, int gtid) {
    const __half* base = g_B1 + (size_t)c * 64 * K1;
    #pragma unroll
    for (int i = gtid; i < 1536; i += 256) {          // 64 rows x 24 x 16B
        int n = i / 24, u = i % 24;
        cpa16(sb + SM_W0S + n * 400 + u * 16, base + n * K1 + u * 8);
    }
    CP_COMMIT();
}
__device__ __forceinline__ void load_w1(uint32_t sb, int c, int gtid) {
    const __half* base = g_B2 + c * 64;
    #pragma unroll
    for (int i = gtid; i < 2048; i += 256) {          // 256 rows x 8 x 16B
        int n = i / 8, u = i % 8;
        cpa16(sb + SM_W1S + n * 144 + u * 16, base + n * HID + u * 8);
    }
    CP_COMMIT();
}

// ---------------- main fused kernel ----------------
__global__ void __launch_bounds__(512, 1)
mlp_kernel(const float* __restrict__ x, const float* __restrict__ b0,
           const float* __restrict__ b1, float* __restrict__ out)
{
    extern __shared__ char smem[];
    const uint32_t sb = smem_u32(smem);
    const int tid  = threadIdx.x;
    const int lane = tid & 31;
    const int w    = tid >> 5;
    const int gtid = tid & 255;
    const int r    = lane >> 2;
    const int q    = lane & 3;
    const bool isA = (w < 8);

    const int slice   = blockIdx.x >> 1;
    const int tokbase = (blockIdx.x & 1) * 64;

    uint32_t*       xsw  = (uint32_t*)(smem + SM_XS);
    const uint32_t* w0sw = (const uint32_t*)(smem + SM_W0S);
    uint32_t*       hsw  = (uint32_t*)(smem + SM_HS);
    const uint32_t* w1sw = (const uint32_t*)(smem + SM_W1S);
    float*          b0s  = (float*)(smem + SM_B0S);
    float*          b1s  = (float*)(smem + SM_B1S);

    if (isA) load_w0(sb, 0, gtid);
    else     load_w1(sb, 0, gtid);

    // X slice -> Xs (fp16, 96 words per row)
    {
        const float2* x2 = (const float2*)(x + (size_t)slice * 24576);
        #pragma unroll 4
        for (int i = tid; i < 6144; i += 512) {
            int m = i / 96, u = i % 96;
            int ch = u >> 5, bp = u & 31;
            float2 v = x2[(ch * 8192 + (tokbase + m) * 64) / 2 + bp];
            xsw[m * XS_W + ch * 32 + bp] = pack2(v.x, v.y);
        }
        for (int i = tid; i < 1024; i += 512) b0s[i] = b0[i];
        for (int i = tid; i < 256;  i += 512) b1s[i] = b1[i];
    }
    __syncthreads();

    if (isA) {
        // ================= group A: GEMM1 producer =================
        const int m1 = (w >> 1) * 16;
        const int n1 = (w & 1) * 32;

        for (int c = 0; c < NCH; c++) {
            const int p = c & 1;
            CP_WAIT0();
            BAR_SYNC(BINTA, 256);

            float c1[4][4];
            #pragma unroll
            for (int j = 0; j < 4; j++)
                #pragma unroll
                for (int e = 0; e < 4; e++) c1[j][e] = 0.0f;

            #pragma unroll 4
            for (int kk = 0; kk < 12; kk++) {
                const int kw = kk * 8;
                const uint32_t* ap = xsw + (m1 + r) * XS_W + kw + q;
                uint32_t a0 = ap[0], a1 = ap[8 * XS_W], a2 = ap[4], a3 = ap[8 * XS_W + 4];
                #pragma unroll
                for (int j = 0; j < 4; j++) {
                    const uint32_t* bp_ = w0sw + (n1 + j * 8 + r) * W0S_W + kw + q;
                    mma16816(c1[j], a0, a1, a2, a3, bp_[0], bp_[4]);
                }
            }
            BAR_SYNC(BINTA, 256);
            if (c + 1 < NCH) load_w0(sb, c + 1, gtid);

            if (c >= 2) BAR_SYNC(BFREE(p), 512);

            // bias + relu + fp16 -> hs[p]
            {
                uint32_t* hsp = hsw + p * 2304;
                const int hb = c * 64;
                #pragma unroll
                for (int j = 0; j < 4; j++) {
                    int n = n1 + j * 8 + q * 2;
                    float bb0 = b0s[hb + n], bb1 = b0s[hb + n + 1];
                    float v0 = fmaxf(c1[j][0] + bb0, 0.f);
                    float v1 = fmaxf(c1[j][1] + bb1, 0.f);
                    float v2 = fmaxf(c1[j][2] + bb0, 0.f);
                    float v3 = fmaxf(c1[j][3] + bb1, 0.f);
                    hsp[(m1 + r) * HS_W + (n >> 1)]     = pack2(v0, v1);
                    hsp[(m1 + r + 8) * HS_W + (n >> 1)] = pack2(v2, v3);
                }
            }
            BAR_ARRIVE(BFULL(p), 512);
        }
    } else {
        // ================= group B: GEMM2 consumer =================
        const int wB = w - 8;
        const int m2 = (wB >> 2) * 32;
        const int n2 = (wB & 3) * 64;

        float acc2[16][4];
        #pragma unroll
        for (int j = 0; j < 16; j++)
            #pragma unroll
            for (int e = 0; e < 4; e++) acc2[j][e] = 0.0f;

        for (int c = 0; c < NCH; c++) {
            const int p = c & 1;
            CP_WAIT0();
            BAR_SYNC(BINTB, 256);
            BAR_SYNC(BFULL(p), 512);

            const uint32_t* hsp = hsw + p * 2304;
            #pragma unroll
            for (int kk = 0; kk < 4; kk++) {
                const int kw = kk * 8;
                uint32_t a[2][4];
                #pragma unroll
                for (int f = 0; f < 2; f++) {
                    const uint32_t* ap = hsp + (m2 + f * 16 + r) * HS_W + kw + q;
                    a[f][0] = ap[0]; a[f][1] = ap[8 * HS_W]; a[f][2] = ap[4]; a[f][3] = ap[8 * HS_W + 4];
                }
                #pragma unroll
                for (int j = 0; j < 8; j++) {
                    const uint32_t* bp_ = w1sw + (n2 + j * 8 + r) * W1S_W + kw + q;
                    uint32_t b0_ = bp_[0], b1_ = bp_[4];
                    #pragma unroll
                    for (int f = 0; f < 2; f++)
                        mma16816(acc2[j * 2 + f], a[f][0], a[f][1], a[f][2], a[f][3], b0_, b1_);
                }
            }
            BAR_SYNC(BINTB, 256);
            if (c + 1 < NCH) load_w1(sb, c + 1, gtid);
            if (c + 2 < NCH) BAR_ARRIVE(BFREE(p), 512);
        }

        // ---- epilogue: +b1, relu, store ----
        #pragma unroll
        for (int j = 0; j < 8; j++) {
            int n = n2 + j * 8 + q * 2;
            float bb0 = b1s[n], bb1 = b1s[n + 1];
            #pragma unroll
            for (int f = 0; f < 2; f++) {
                const int rowg = slice * 128 + tokbase + m2 + f * 16 + r;
                float2 o0, o1;
                o0.x = fmaxf(acc2[j * 2 + f][0] + bb0, 0.f);
                o0.y = fmaxf(acc2[j * 2 + f][1] + bb1, 0.f);
                o1.x = fmaxf(acc2[j * 2 + f][2] + bb0, 0.f);
                o1.y = fmaxf(acc2[j * 2 + f][3] + bb1, 0.f);
                *(float2*)(out + (size_t)rowg * 256 + n)       = o0;
                *(float2*)(out + (size_t)(rowg + 8) * 256 + n) = o1;
            }
        }
    }
}

extern "C" void kernel_launch(void* const* d_in, const int* in_sizes, int n_in,
                              void* d_out, int out_size)
{
    const float* x  = (const float*)d_in[0];
    const float* W0 = (const float*)d_in[1];
    const float* b0 = (const float*)d_in[2];
    const float* W1 = (const float*)d_in[3];
    const float* b1 = (const float*)d_in[4];
    float* out = (float*)d_out;

    static bool configured = false;
    if (!configured) {
        cudaFuncSetAttribute(mlp_kernel,
                             cudaFuncAttributeMaxDynamicSharedMemorySize, SM_TOTAL);
        configured = true;
    }
    prep_kernel<<<256, 256>>>(W0, W1);
    mlp_kernel<<<3072, 512, SM_TOTAL>>>(x, b0, b1, out);
}

// round 11
// speedup vs baseline: 7.4869x; 1.1026x over previous
#include <cuda_runtime.h>
#include <cuda_fp16.h>
#include <cstdint>

// Fused 2-layer MLP, pure fp16 mma.sync, unified 256-thread CTA tuned for
// 2 CTAs/SM (cross-CTA phase overlap replaces warp specialization).
//   out = relu(relu(X@W0+b0)@W1+b1)
// rel_err budget (validated R8/R9): ~4.2e-4 < 1e-3.
// (R11 = identical resubmit of R10 after infra failure.)

#define K1   192
#define HID  1024
#define EMB  256
#define NCH  16

#define XS_W  100     // words/row Xs: 192 fp16 = 96 w + 4 pad (100%32=4)
#define W0S_W 100
#define HS_W  36      // words/row hs: 64 fp16 = 32 w + 4 pad
#define W1S_W 36

// smem byte offsets (total 100 KB -> 2 CTAs/SM)
#define SM_B0S 0                      // 4096
#define SM_B1S 4096                   // 1024
#define SM_XS  5120                   // 64*400  = 25600
#define SM_W0S 30720                  // 64*400  = 25600
#define SM_HS  56320                  // 64*144  = 9216
#define SM_W1S 65536                  // 256*144 = 36864
#define SM_TOTAL 102400

// Pre-transposed fp16 weights, [n][k] k-major
__device__ __align__(16) __half g_B1[HID * K1];     // W0^T
__device__ __align__(16) __half g_B2[EMB * HID];    // W1^T

__device__ __forceinline__ void cpa16(uint32_t dst, const void* src) {
    asm volatile("cp.async.cg.shared.global [%0], [%1], 16;" :: "r"(dst), "l"(src) : "memory");
}
#define CP_COMMIT() asm volatile("cp.async.commit_group;" ::: "memory")
#define CP_WAIT1()  asm volatile("cp.async.wait_group 1;" ::: "memory")
#define CP_WAIT0()  asm volatile("cp.async.wait_group 0;" ::: "memory")

__device__ __forceinline__ uint32_t smem_u32(const void* p) {
    uint32_t a;
    asm("{ .reg .u64 t; cvta.to.shared.u64 t, %1; cvt.u32.u64 %0, t; }" : "=r"(a) : "l"(p));
    return a;
}

__device__ __forceinline__ void mma16816(float* c,
    uint32_t a0, uint32_t a1, uint32_t a2, uint32_t a3, uint32_t b0, uint32_t b1)
{
    asm volatile("mma.sync.aligned.m16n8k16.row.col.f32.f16.f16.f32 "
        "{%0,%1,%2,%3}, {%4,%5,%6,%7}, {%8,%9}, {%0,%1,%2,%3};"
        : "+f"(c[0]), "+f"(c[1]), "+f"(c[2]), "+f"(c[3])
        : "r"(a0), "r"(a1), "r"(a2), "r"(a3), "r"(b0), "r"(b1));
}

__device__ __forceinline__ uint32_t pack2(float x, float y) {
    __half2 h = __halves2half2(__float2half_rn(x), __float2half_rn(y));
    return *(uint32_t*)&h;
}

// ---------------- weight prep: fp16, transposed to [n][k] ----------------
__global__ void prep_kernel(const float* __restrict__ W0, const float* __restrict__ W1) {
    int stride = gridDim.x * blockDim.x;
    int t0 = blockIdx.x * blockDim.x + threadIdx.x;
    for (int i = t0; i < HID * K1; i += stride) {
        int n = i / K1, k = i % K1;
        g_B1[n * K1 + k] = __float2half_rn(W0[k * HID + n]);
    }
    for (int i = t0; i < EMB * HID; i += stride) {
        int n = i / HID, k = i % HID;
        g_B2[n * HID + k] = __float2half_rn(W1[k * EMB + n]);
    }
}

// ---------------- chunk loaders (256 threads) ----------------
__device__ __forceinline__ void load_w0(uint32_t sb, int c, int tid) {
    const __half* base = g_B1 + (size_t)c * 64 * K1;
    #pragma unroll
    for (int i = tid; i < 1536; i += 256) {           // 64 rows x 24 x 16B
        int n = i / 24, u = i % 24;
        cpa16(sb + SM_W0S + n * 400 + u * 16, base + n * K1 + u * 8);
    }
    CP_COMMIT();
}
__device__ __forceinline__ void load_w1(uint32_t sb, int c, int tid) {
    const __half* base = g_B2 + c * 64;
    #pragma unroll
    for (int i = tid; i < 2048; i += 256) {           // 256 rows x 8 x 16B
        int n = i / 8, u = i % 8;
        cpa16(sb + SM_W1S + n * 144 + u * 16, base + n * HID + u * 8);
    }
    CP_COMMIT();
}

// ---------------- main fused kernel ----------------
__global__ void __launch_bounds__(256, 2)
mlp_kernel(const float* __restrict__ x, const float* __restrict__ b0,
           const float* __restrict__ b1, float* __restrict__ out)
{
    extern __shared__ char smem[];
    const uint32_t sb = smem_u32(smem);
    const int tid  = threadIdx.x;
    const int lane = tid & 31;
    const int w    = tid >> 5;
    const int r    = lane >> 2;
    const int q    = lane & 3;

    // GEMM1 warp tile 16x32; GEMM2 warp tile 32x64
    const int m1 = (w >> 1) * 16;
    const int n1 = (w & 1) * 32;
    const int m2 = (w >> 2) * 32;
    const int n2 = (w & 3) * 64;

    const int slice   = blockIdx.x >> 1;
    const int tokbase = (blockIdx.x & 1) * 64;

    uint32_t*       xsw  = (uint32_t*)(smem + SM_XS);
    const uint32_t* w0sw = (const uint32_t*)(smem + SM_W0S);
    uint32_t*       hsw  = (uint32_t*)(smem + SM_HS);
    const uint32_t* w1sw = (const uint32_t*)(smem + SM_W1S);
    float*          b0s  = (float*)(smem + SM_B0S);
    float*          b1s  = (float*)(smem + SM_B1S);

    // prefetch chunk 0 weights
    load_w0(sb, 0, tid);
    load_w1(sb, 0, tid);

    // X slice -> Xs (fp16, 96 words per row)
    {
        const float2* x2 = (const float2*)(x + (size_t)slice * 24576);
        #pragma unroll 4
        for (int i = tid; i < 6144; i += 256) {
            int m = i / 96, u = i % 96;
            int ch = u >> 5, bp = u & 31;
            float2 v = x2[(ch * 8192 + (tokbase + m) * 64) / 2 + bp];
            xsw[m * XS_W + ch * 32 + bp] = pack2(v.x, v.y);
        }
        for (int i = tid; i < 1024; i += 256) b0s[i] = b0[i];
        for (int i = tid; i < 256;  i += 256) b1s[i] = b1[i];
    }

    float acc2[16][4];
    #pragma unroll
    for (int j = 0; j < 16; j++)
        #pragma unroll
        for (int e = 0; e < 4; e++) acc2[j][e] = 0.0f;

    for (int c = 0; c < NCH; c++) {
        CP_WAIT1();                  // w0(c) resident (w1(c) may be in flight)
        __syncthreads();

        // ---- GEMM1: c1[16x32 per warp], k = 192 ----
        float c1[4][4];
        #pragma unroll
        for (int j = 0; j < 4; j++)
            #pragma unroll
            for (int e = 0; e < 4; e++) c1[j][e] = 0.0f;

        #pragma unroll 4
        for (int kk = 0; kk < 12; kk++) {
            const int kw = kk * 8;
            const uint32_t* ap = xsw + (m1 + r) * XS_W + kw + q;
            uint32_t a0 = ap[0], a1 = ap[8 * XS_W], a2 = ap[4], a3 = ap[8 * XS_W + 4];
            #pragma unroll
            for (int j = 0; j < 4; j++) {
                const uint32_t* bp_ = w0sw + (n1 + j * 8 + r) * W0S_W + kw + q;
                mma16816(c1[j], a0, a1, a2, a3, bp_[0], bp_[4]);
            }
        }

        // ---- bias + relu + fp16 -> hs ----
        {
            const int hb = c * 64;
            #pragma unroll
            for (int j = 0; j < 4; j++) {
                int n = n1 + j * 8 + q * 2;
                float bb0 = b0s[hb + n], bb1 = b0s[hb + n + 1];
                float v0 = fmaxf(c1[j][0] + bb0, 0.f);
                float v1 = fmaxf(c1[j][1] + bb1, 0.f);
                float v2 = fmaxf(c1[j][2] + bb0, 0.f);
                float v3 = fmaxf(c1[j][3] + bb1, 0.f);
                hsw[(m1 + r) * HS_W + (n >> 1)]     = pack2(v0, v1);
                hsw[(m1 + r + 8) * HS_W + (n >> 1)] = pack2(v2, v3);
            }
        }
        __syncthreads();             // w0s free, hs published
        if (c + 1 < NCH) load_w0(sb, c + 1, tid);

        if (c + 1 < NCH) { CP_WAIT1(); } else { CP_WAIT0(); }  // w1(c) resident
        __syncthreads();

        // ---- GEMM2: acc2[32x64 per warp] += hs @ w1s ----
        #pragma unroll
        for (int kk = 0; kk < 4; kk++) {
            const int kw = kk * 8;
            uint32_t a[2][4];
            #pragma unroll
            for (int f = 0; f < 2; f++) {
                const uint32_t* ap = hsw + (m2 + f * 16 + r) * HS_W + kw + q;
                a[f][0] = ap[0]; a[f][1] = ap[8 * HS_W]; a[f][2] = ap[4]; a[f][3] = ap[8 * HS_W + 4];
            }
            #pragma unroll
            for (int j = 0; j < 8; j++) {
                const uint32_t* bp_ = w1sw + (n2 + j * 8 + r) * W1S_W + kw + q;
                uint32_t b0_ = bp_[0], b1_ = bp_[4];
                #pragma unroll
                for (int f = 0; f < 2; f++)
                    mma16816(acc2[j * 2 + f], a[f][0], a[f][1], a[f][2], a[f][3], b0_, b1_);
            }
        }
        __syncthreads();             // w1s + hs free
        if (c + 1 < NCH) load_w1(sb, c + 1, tid);
    }

    // ---- epilogue: +b1, relu, store ----
    #pragma unroll
    for (int j = 0; j < 8; j++) {
        int n = n2 + j * 8 + q * 2;
        float bb0 = b1s[n], bb1 = b1s[n + 1];
        #pragma unroll
        for (int f = 0; f < 2; f++) {
            const int rowg = slice * 128 + tokbase + m2 + f * 16 + r;
            float2 o0, o1;
            o0.x = fmaxf(acc2[j * 2 + f][0] + bb0, 0.f);
            o0.y = fmaxf(acc2[j * 2 + f][1] + bb1, 0.f);
            o1.x = fmaxf(acc2[j * 2 + f][2] + bb0, 0.f);
            o1.y = fmaxf(acc2[j * 2 + f][3] + bb1, 0.f);
            *(float2*)(out + (size_t)rowg * 256 + n)       = o0;
            *(float2*)(out + (size_t)(rowg + 8) * 256 + n) = o1;
        }
    }
}

extern "C" void kernel_launch(void* const* d_in, const int* in_sizes, int n_in,
                              void* d_out, int out_size)
{
    const float* x  = (const float*)d_in[0];
    const float* W0 = (const float*)d_in[1];
    const float* b0 = (const float*)d_in[2];
    const float* W1 = (const float*)d_in[3];
    const float* b1 = (const float*)d_in[4];
    float* out = (float*)d_out;

    static bool configured = false;
    if (!configured) {
        cudaFuncSetAttribute(mlp_kernel,
                             cudaFuncAttributeMaxDynamicSharedMemorySize, SM_TOTAL);
        configured = true;
    }
    prep_kernel<<<256, 256>>>(W0, W1);
    mlp_kernel<<<3072, 256, SM_TOTAL>>>(x, b0, b1, out);
}